// round 3
// baseline (speedup 1.0000x reference)
#include <cuda_runtime.h>
#include <cstdint>
#include <cstddef>

#define N_NODES 100000
#define N_EDGES 3200000
#define IN_DIM  256
#define HID     128
#define OUT_DIM 2
#define BN_EPS  1e-5f

// ---------------- scratch (static device globals; no runtime alloc) --------
__device__ __align__(16) float g_dinv[N_NODES];               // rsqrt(deg)
__device__ __align__(16) float g_h1s[(size_t)N_NODES * HID];  // h1 * dinv[row]
__device__ __align__(16) float g_acc[(size_t)N_NODES * HID];  // aggregated hidden
__device__ __align__(16) float g_h2s[N_NODES * OUT_DIM];      // h2 * dinv[row]
__device__ __align__(16) float g_W1s[IN_DIM * HID];           // W1 * sigmoid(fi)
__device__ __align__(16) float g_sums[HID];
__device__ __align__(16) float g_sumsq[HID];
__device__ __align__(16) float g_scale[HID];
__device__ __align__(16) float g_shift[HID];
// CSR by destination
__device__ __align__(16) int   g_cnt[N_NODES];
__device__ __align__(16) int   g_off[N_NODES + 1];
__device__ __align__(16) int   g_cursor[N_NODES];
__device__ __align__(16) int   g_csr_row[N_EDGES];

// ---------------- K0: prep (fold sigmoid into W1, zero counters) -----------
__global__ void k_prep(const float* __restrict__ W1, const float* __restrict__ fi) {
    int i = blockIdx.x * blockDim.x + threadIdx.x;
    if (i < IN_DIM * HID) {
        int k = i / HID;
        float s = 1.0f / (1.0f + __expf(-fi[k]));
        g_W1s[i] = W1[i] * s;
    }
    if (i < N_NODES) g_cnt[i] = 0;
    if (i < HID) { g_sums[i] = 0.0f; g_sumsq[i] = 0.0f; }
}

// ---------------- K1: in-degree histogram (edge_index is INT32) -------------
__global__ void k_deg(const int* __restrict__ ei) {
    int e = blockIdx.x * blockDim.x + threadIdx.x;
    if (e < N_EDGES) {
        int c = ei[N_EDGES + e];   // col
        atomicAdd(&g_cnt[c], 1);
    }
}

// ---------------- K2: single-block scan -> offsets, cursor, dinv ------------
__global__ __launch_bounds__(1024) void k_scan() {
    __shared__ int partial[1024];
    const int t = threadIdx.x;
    const int CHUNK = (N_NODES + 1023) / 1024;  // 98
    int s0 = t * CHUNK;
    int s1 = s0 + CHUNK; if (s1 > N_NODES) s1 = N_NODES;
    int sum = 0;
    for (int i = s0; i < s1; ++i) sum += g_cnt[i];
    partial[t] = sum;
    __syncthreads();
    for (int off = 1; off < 1024; off <<= 1) {
        int v = (t >= off) ? partial[t - off] : 0;
        __syncthreads();
        partial[t] += v;
        __syncthreads();
    }
    int run = partial[t] - sum;  // exclusive prefix of this chunk
    for (int i = s0; i < s1; ++i) {
        int c = g_cnt[i];
        g_off[i] = run;
        g_cursor[i] = run;
        g_dinv[i] = rsqrtf((float)(c + 1));   // +1 self loop
        run += c;
    }
    if (t == 1023) g_off[N_NODES] = run;
}

// ---------------- K3: fill CSR source indices --------------------------------
__global__ void k_fill(const int* __restrict__ ei) {
    int e = blockIdx.x * blockDim.x + threadIdx.x;
    if (e >= N_EDGES) return;
    int r = ei[e];
    int c = ei[N_EDGES + e];
    int pos = atomicAdd(&g_cursor[c], 1);
    g_csr_row[pos] = r;
}

// ---------------- K4: GEMM1: h1s = (x @ W1s) * dinv[row] --------------------
#define BM 64
#define BK 32
__global__ __launch_bounds__(256) void k_gemm1(const float* __restrict__ x) {
    __shared__ float As[BK][BM + 1];
    __shared__ float Bs[BK][HID];
    const int m0 = blockIdx.x * BM;
    const int tid = threadIdx.x;
    const int tr = tid >> 5;
    const int tc = tid & 31;

    float acc[8][4] = {};

    for (int k0 = 0; k0 < IN_DIM; k0 += BK) {
        #pragma unroll
        for (int p = 0; p < 2; ++p) {
            int slot = tid + p * 256;
            int r = slot >> 3;
            int kq = slot & 7;
            int gm = m0 + r;
            float4 v = make_float4(0.f, 0.f, 0.f, 0.f);
            if (gm < N_NODES)
                v = *(const float4*)(x + (size_t)gm * IN_DIM + k0 + kq * 4);
            As[kq * 4 + 0][r] = v.x;
            As[kq * 4 + 1][r] = v.y;
            As[kq * 4 + 2][r] = v.z;
            As[kq * 4 + 3][r] = v.w;
        }
        #pragma unroll
        for (int p = 0; p < 4; ++p) {
            int slot = tid + p * 256;
            int r  = slot >> 5;
            int cq = slot & 31;
            float4 v = *(const float4*)(g_W1s + (size_t)(k0 + r) * HID + cq * 4);
            *(float4*)&Bs[r][cq * 4] = v;
        }
        __syncthreads();
        #pragma unroll
        for (int kk = 0; kk < BK; ++kk) {
            float a[8], b[4];
            #pragma unroll
            for (int i = 0; i < 8; ++i) a[i] = As[kk][tr * 8 + i];
            #pragma unroll
            for (int j = 0; j < 4; ++j) b[j] = Bs[kk][tc * 4 + j];
            #pragma unroll
            for (int i = 0; i < 8; ++i)
                #pragma unroll
                for (int j = 0; j < 4; ++j)
                    acc[i][j] = fmaf(a[i], b[j], acc[i][j]);
        }
        __syncthreads();
    }
    #pragma unroll
    for (int i = 0; i < 8; ++i) {
        int gm = m0 + tr * 8 + i;
        if (gm >= N_NODES) continue;
        float d = g_dinv[gm];
        float4 v = make_float4(acc[i][0] * d, acc[i][1] * d, acc[i][2] * d, acc[i][3] * d);
        *(float4*)(g_h1s + (size_t)gm * HID + tc * 4) = v;
    }
}

// ---------------- K5: layer-1 aggregation (gather, warp per node) -----------
__global__ __launch_bounds__(256) void k_agg1() {
    int n = (blockIdx.x * blockDim.x + threadIdx.x) >> 5;
    int lane = threadIdx.x & 31;
    if (n >= N_NODES) return;
    int s = g_off[n], e = g_off[n + 1];
    // self loop seed
    float4 v0 = *(const float4*)(g_h1s + (size_t)n * HID + lane * 4);
    float4 v1 = make_float4(0.f, 0.f, 0.f, 0.f);
    int i = s;
    for (; i + 2 <= e; i += 2) {
        int r0 = g_csr_row[i];
        int r1 = g_csr_row[i + 1];
        float4 u0 = *(const float4*)(g_h1s + (size_t)r0 * HID + lane * 4);
        float4 u1 = *(const float4*)(g_h1s + (size_t)r1 * HID + lane * 4);
        v0.x += u0.x; v0.y += u0.y; v0.z += u0.z; v0.w += u0.w;
        v1.x += u1.x; v1.y += u1.y; v1.z += u1.z; v1.w += u1.w;
    }
    if (i < e) {
        int r0 = g_csr_row[i];
        float4 u0 = *(const float4*)(g_h1s + (size_t)r0 * HID + lane * 4);
        v0.x += u0.x; v0.y += u0.y; v0.z += u0.z; v0.w += u0.w;
    }
    v0.x += v1.x; v0.y += v1.y; v0.z += v1.z; v0.w += v1.w;
    *(float4*)(g_acc + (size_t)n * HID + lane * 4) = v0;
}

// ---------------- K6: BN statistics ------------------------------------------
__global__ __launch_bounds__(128) void k_bnsum(const float* __restrict__ b1) {
    int j = threadIdx.x;
    float bj = __ldg(b1 + j);
    float s = 0.f, s2 = 0.f;
    for (int n = blockIdx.x; n < N_NODES; n += gridDim.x) {
        float v = g_dinv[n] * g_acc[(size_t)n * HID + j] + bj;
        s += v;
        s2 += v * v;
    }
    atomicAdd(&g_sums[j], s);
    atomicAdd(&g_sumsq[j], s2);
}

// ---------------- K7: finalize BN affine -------------------------------------
__global__ void k_bnfin(const float* __restrict__ gamma, const float* __restrict__ beta) {
    int j = threadIdx.x;
    if (j >= HID) return;
    float inv_n = 1.0f / (float)N_NODES;
    float mu = g_sums[j] * inv_n;
    float var = g_sumsq[j] * inv_n - mu * mu;
    float inv = rsqrtf(var + BN_EPS);
    float sc = __ldg(gamma + j) * inv;
    g_scale[j] = sc;
    g_shift[j] = __ldg(beta + j) - mu * sc;
}

// ---------------- K8: BN + relu + 128->2 GEMV, pre-scaled by dinv[row] ------
__global__ __launch_bounds__(256) void k_node2(const float* __restrict__ b1,
                                               const float* __restrict__ W2) {
    int n = (blockIdx.x * blockDim.x + threadIdx.x) >> 5;
    int lane = threadIdx.x & 31;
    if (n >= N_NODES) return;
    float d = g_dinv[n];
    float4 v = *(const float4*)(g_acc + (size_t)n * HID + lane * 4);
    float vv[4] = {v.x, v.y, v.z, v.w};
    float o0 = 0.f, o1 = 0.f;
    #pragma unroll
    for (int q = 0; q < 4; ++q) {
        int j = lane * 4 + q;
        float h = fmaf(d * vv[q] + __ldg(b1 + j), g_scale[j], g_shift[j]);
        h = fmaxf(h, 0.f);
        o0 = fmaf(h, __ldg(W2 + j * 2 + 0), o0);
        o1 = fmaf(h, __ldg(W2 + j * 2 + 1), o1);
    }
    #pragma unroll
    for (int off = 16; off > 0; off >>= 1) {
        o0 += __shfl_xor_sync(0xffffffffu, o0, off);
        o1 += __shfl_xor_sync(0xffffffffu, o1, off);
    }
    if (lane == 0) {
        g_h2s[n * 2 + 0] = o0 * d;   // pre-scale by dinv[row]
        g_h2s[n * 2 + 1] = o1 * d;
    }
}

// ---------------- K9: layer-2 aggregation (gather) + bias -------------------
__global__ __launch_bounds__(256) void k_out(const float* __restrict__ b2,
                                             float* __restrict__ out) {
    int n = (blockIdx.x * blockDim.x + threadIdx.x) >> 5;
    int lane = threadIdx.x & 31;
    if (n >= N_NODES) return;
    int s = g_off[n], e = g_off[n + 1];
    float o0 = 0.f, o1 = 0.f;
    for (int i = s + lane; i < e; i += 32) {
        int r = g_csr_row[i];
        float2 v = *(const float2*)(g_h2s + (size_t)r * 2);
        o0 += v.x; o1 += v.y;
    }
    #pragma unroll
    for (int off = 16; off > 0; off >>= 1) {
        o0 += __shfl_xor_sync(0xffffffffu, o0, off);
        o1 += __shfl_xor_sync(0xffffffffu, o1, off);
    }
    if (lane == 0) {
        float d = g_dinv[n];
        float2 self = *(const float2*)(g_h2s + (size_t)n * 2);
        out[n * 2 + 0] = d * (o0 + self.x) + __ldg(b2 + 0);
        out[n * 2 + 1] = d * (o1 + self.y) + __ldg(b2 + 1);
    }
}

// ---------------- launch ----------------------------------------------------
extern "C" void kernel_launch(void* const* d_in, const int* in_sizes, int n_in,
                              void* d_out, int out_size) {
    const float* x  = (const float*)d_in[0];
    const int*   ei = (const int*)d_in[1];     // edge_index is int32 (JAX x64 off)
    const float* fi = (const float*)d_in[2];
    const float* W1 = (const float*)d_in[3];
    const float* b1 = (const float*)d_in[4];
    const float* W2 = (const float*)d_in[5];
    const float* b2 = (const float*)d_in[6];
    const float* gm = (const float*)d_in[7];
    const float* bt = (const float*)d_in[8];
    float* out = (float*)d_out;

    k_prep<<<(N_NODES + 255) / 256, 256>>>(W1, fi);
    k_deg<<<(N_EDGES + 255) / 256, 256>>>(ei);
    k_scan<<<1, 1024>>>();
    k_fill<<<(N_EDGES + 255) / 256, 256>>>(ei);
    k_gemm1<<<(N_NODES + BM - 1) / BM, 256>>>(x);
    {
        long long tot = (long long)N_NODES * 32;
        k_agg1<<<(unsigned)((tot + 255) / 256), 256>>>();
    }
    k_bnsum<<<1024, 128>>>(b1);
    k_bnfin<<<1, 128>>>(gm, bt);
    {
        long long tot = (long long)N_NODES * 32;
        k_node2<<<(unsigned)((tot + 255) / 256), 256>>>(b1, W2);
        k_out<<<(unsigned)((tot + 255) / 256), 256>>>(b2, out);
    }
}

// round 4
// speedup vs baseline: 1.1663x; 1.1663x over previous
#include <cuda_runtime.h>
#include <cstdint>
#include <cstddef>

#define N_NODES 100000
#define N_EDGES 3200000
#define IN_DIM  256
#define HID     128
#define OUT_DIM 2
#define BN_EPS  1e-5f

// ---------------- scratch (static device globals; no runtime alloc) --------
__device__ __align__(16) float g_dinv[N_NODES];               // rsqrt(deg)
__device__ __align__(16) float g_h1s[(size_t)N_NODES * HID];  // h1 * dinv[row]
__device__ __align__(16) float g_acc[(size_t)N_NODES * HID];  // aggregated hidden
__device__ __align__(16) float g_h2s[N_NODES * OUT_DIM];      // h2 * dinv[row]
__device__ __align__(16) float g_W1s[IN_DIM * HID];           // W1 * sigmoid(fi)
__device__ __align__(16) float g_sums[HID];
__device__ __align__(16) float g_sumsq[HID];
__device__ __align__(16) float g_scale[HID];
__device__ __align__(16) float g_shift[HID];
// CSR by destination
__device__ __align__(16) int   g_cnt[N_NODES];
__device__ __align__(16) int   g_off[N_NODES + 1];
__device__ __align__(16) int   g_cursor[N_NODES];
__device__ __align__(16) int   g_csr_row[N_EDGES];

// ---------------- helpers ---------------------------------------------------
__device__ __forceinline__ float to_tf32(float x) {
    uint32_t u;
    asm("cvt.rna.tf32.f32 %0, %1;" : "=r"(u) : "f"(x));
    return __uint_as_float(u);
}

__device__ __forceinline__ void mma_tf32(float* c,
                                         uint32_t a0, uint32_t a1, uint32_t a2, uint32_t a3,
                                         uint32_t b0, uint32_t b1) {
    asm volatile(
        "mma.sync.aligned.m16n8k8.row.col.f32.tf32.tf32.f32 "
        "{%0,%1,%2,%3}, {%4,%5,%6,%7}, {%8,%9}, {%0,%1,%2,%3};"
        : "+f"(c[0]), "+f"(c[1]), "+f"(c[2]), "+f"(c[3])
        : "r"(a0), "r"(a1), "r"(a2), "r"(a3), "r"(b0), "r"(b1));
}

// ---------------- K0: prep (fold sigmoid into W1, zero counters) -----------
__global__ void k_prep(const float* __restrict__ W1, const float* __restrict__ fi) {
    int i = blockIdx.x * blockDim.x + threadIdx.x;
    if (i < IN_DIM * HID) {
        int k = i / HID;
        float s = 1.0f / (1.0f + __expf(-fi[k]));
        g_W1s[i] = W1[i] * s;
    }
    if (i < N_NODES) g_cnt[i] = 0;
    if (i < HID) { g_sums[i] = 0.0f; g_sumsq[i] = 0.0f; }
}

// ---------------- K1: in-degree histogram (4 edges per thread) --------------
__global__ void k_deg(const int* __restrict__ ei) {
    int t = blockIdx.x * blockDim.x + threadIdx.x;
    int e4 = t * 4;
    if (e4 >= N_EDGES) return;
    int4 c = *(const int4*)(ei + N_EDGES + e4);
    atomicAdd(&g_cnt[c.x], 1);
    atomicAdd(&g_cnt[c.y], 1);
    atomicAdd(&g_cnt[c.z], 1);
    atomicAdd(&g_cnt[c.w], 1);
}

// ---------------- K2: single-block scan -> offsets, cursor, dinv ------------
__global__ __launch_bounds__(1024) void k_scan() {
    __shared__ int partial[1024];
    const int t = threadIdx.x;
    const int CHUNK = (N_NODES + 1023) / 1024;
    int s0 = t * CHUNK;
    int s1 = s0 + CHUNK; if (s1 > N_NODES) s1 = N_NODES;
    int sum = 0;
    for (int i = s0; i < s1; ++i) sum += g_cnt[i];
    partial[t] = sum;
    __syncthreads();
    for (int off = 1; off < 1024; off <<= 1) {
        int v = (t >= off) ? partial[t - off] : 0;
        __syncthreads();
        partial[t] += v;
        __syncthreads();
    }
    int run = partial[t] - sum;
    for (int i = s0; i < s1; ++i) {
        int c = g_cnt[i];
        g_off[i] = run;
        g_cursor[i] = run;
        g_dinv[i] = rsqrtf((float)(c + 1));
        run += c;
    }
    if (t == 1023) g_off[N_NODES] = run;
}

// ---------------- K3: fill CSR source indices (4 edges per thread) ----------
__global__ void k_fill(const int* __restrict__ ei) {
    int t = blockIdx.x * blockDim.x + threadIdx.x;
    int e4 = t * 4;
    if (e4 >= N_EDGES) return;
    int4 r = *(const int4*)(ei + e4);
    int4 c = *(const int4*)(ei + N_EDGES + e4);
    int p0 = atomicAdd(&g_cursor[c.x], 1);
    int p1 = atomicAdd(&g_cursor[c.y], 1);
    int p2 = atomicAdd(&g_cursor[c.z], 1);
    int p3 = atomicAdd(&g_cursor[c.w], 1);
    g_csr_row[p0] = r.x;
    g_csr_row[p1] = r.y;
    g_csr_row[p2] = r.z;
    g_csr_row[p3] = r.w;
}

// ---------------- K4: GEMM1 (tf32 tensor cores): h1s = (x @ W1s)*dinv[row] --
// Block tile 128x128, BK=32. 8 warps arranged 2(m) x 4(n); warp tile 64x32.
#define GBM 128
#define GBK 32
#define A_S 36    // padded stride (words) -> conflict-free frag loads
#define B_S 132
__global__ __launch_bounds__(256) void k_gemm1(const float* __restrict__ x) {
    __shared__ float As[GBM * A_S];        // [m][k]  128 x 36
    __shared__ float Bs[GBK * B_S];        // [k][n]  32 x 132
    const int m0   = blockIdx.x * GBM;
    const int tid  = threadIdx.x;
    const int lane = tid & 31;
    const int wid  = tid >> 5;
    const int wm   = wid >> 2;             // 0..1
    const int wn   = wid & 3;              // 0..3
    const int grp  = lane >> 2;            // groupID 0..7
    const int tg   = lane & 3;             // thread-in-group

    float acc[4][4][4];
    #pragma unroll
    for (int im = 0; im < 4; ++im)
        #pragma unroll
        for (int in = 0; in < 4; ++in)
            #pragma unroll
            for (int q = 0; q < 4; ++q) acc[im][in][q] = 0.f;

    for (int k0 = 0; k0 < IN_DIM; k0 += GBK) {
        // load A tile: 128 rows x 32 cols = 1024 float4, 4 per thread
        #pragma unroll
        for (int p = 0; p < 4; ++p) {
            int slot = tid + p * 256;
            int r = slot >> 3;             // 0..127
            int q = slot & 7;              // float4 index in k
            int gm = m0 + r;
            float4 v = make_float4(0.f, 0.f, 0.f, 0.f);
            if (gm < N_NODES)
                v = *(const float4*)(x + (size_t)gm * IN_DIM + k0 + q * 4);
            float* dst = As + r * A_S + q * 4;
            dst[0] = to_tf32(v.x);
            dst[1] = to_tf32(v.y);
            dst[2] = to_tf32(v.z);
            dst[3] = to_tf32(v.w);
        }
        // load B tile: 32 rows x 128 cols = 1024 float4, 4 per thread
        #pragma unroll
        for (int p = 0; p < 4; ++p) {
            int slot = tid + p * 256;
            int r = slot >> 5;             // k row 0..31
            int c = slot & 31;             // float4 col
            float4 v = *(const float4*)(g_W1s + (size_t)(k0 + r) * HID + c * 4);
            float* dst = Bs + r * B_S + c * 4;
            dst[0] = to_tf32(v.x);
            dst[1] = to_tf32(v.y);
            dst[2] = to_tf32(v.z);
            dst[3] = to_tf32(v.w);
        }
        __syncthreads();

        #pragma unroll
        for (int ks = 0; ks < GBK; ks += 8) {
            uint32_t a[4][4], b[4][2];
            #pragma unroll
            for (int im = 0; im < 4; ++im) {
                int mb = wm * 64 + im * 16;
                const float* pa = As + (mb + grp) * A_S + ks + tg;
                a[im][0] = __float_as_uint(pa[0]);
                a[im][1] = __float_as_uint(pa[8 * A_S]);
                a[im][2] = __float_as_uint(pa[4]);
                a[im][3] = __float_as_uint(pa[8 * A_S + 4]);
            }
            #pragma unroll
            for (int in = 0; in < 4; ++in) {
                int nb = wn * 32 + in * 8 + grp;
                const float* pb = Bs + (ks + tg) * B_S + nb;
                b[in][0] = __float_as_uint(pb[0]);
                b[in][1] = __float_as_uint(pb[4 * B_S]);
            }
            #pragma unroll
            for (int im = 0; im < 4; ++im)
                #pragma unroll
                for (int in = 0; in < 4; ++in)
                    mma_tf32(acc[im][in], a[im][0], a[im][1], a[im][2], a[im][3],
                             b[in][0], b[in][1]);
        }
        __syncthreads();
    }

    // epilogue: scale by dinv[row], write h1s
    #pragma unroll
    for (int im = 0; im < 4; ++im) {
        int r0 = m0 + wm * 64 + im * 16 + grp;   // c0/c1 row
        int r1 = r0 + 8;                          // c2/c3 row
        float d0 = (r0 < N_NODES) ? g_dinv[r0] : 0.f;
        float d1 = (r1 < N_NODES) ? g_dinv[r1] : 0.f;
        #pragma unroll
        for (int in = 0; in < 4; ++in) {
            int col = wn * 32 + in * 8 + tg * 2;
            if (r0 < N_NODES) {
                float2 v = make_float2(acc[im][in][0] * d0, acc[im][in][1] * d0);
                *(float2*)(g_h1s + (size_t)r0 * HID + col) = v;
            }
            if (r1 < N_NODES) {
                float2 v = make_float2(acc[im][in][2] * d1, acc[im][in][3] * d1);
                *(float2*)(g_h1s + (size_t)r1 * HID + col) = v;
            }
        }
    }
}

// ---------------- K5: layer-1 aggregation (gather, warp per node) -----------
__global__ __launch_bounds__(256) void k_agg1() {
    int n = (blockIdx.x * blockDim.x + threadIdx.x) >> 5;
    int lane = threadIdx.x & 31;
    if (n >= N_NODES) return;
    int s = g_off[n], e = g_off[n + 1];
    float4 v0 = *(const float4*)(g_h1s + (size_t)n * HID + lane * 4);
    float4 v1 = make_float4(0.f, 0.f, 0.f, 0.f);
    int i = s;
    for (; i + 2 <= e; i += 2) {
        int r0 = g_csr_row[i];
        int r1 = g_csr_row[i + 1];
        float4 u0 = *(const float4*)(g_h1s + (size_t)r0 * HID + lane * 4);
        float4 u1 = *(const float4*)(g_h1s + (size_t)r1 * HID + lane * 4);
        v0.x += u0.x; v0.y += u0.y; v0.z += u0.z; v0.w += u0.w;
        v1.x += u1.x; v1.y += u1.y; v1.z += u1.z; v1.w += u1.w;
    }
    if (i < e) {
        int r0 = g_csr_row[i];
        float4 u0 = *(const float4*)(g_h1s + (size_t)r0 * HID + lane * 4);
        v0.x += u0.x; v0.y += u0.y; v0.z += u0.z; v0.w += u0.w;
    }
    v0.x += v1.x; v0.y += v1.y; v0.z += v1.z; v0.w += v1.w;
    *(float4*)(g_acc + (size_t)n * HID + lane * 4) = v0;
}

// ---------------- K6: BN statistics ------------------------------------------
__global__ __launch_bounds__(128) void k_bnsum(const float* __restrict__ b1) {
    int j = threadIdx.x;
    float bj = __ldg(b1 + j);
    float s = 0.f, s2 = 0.f;
    for (int n = blockIdx.x; n < N_NODES; n += gridDim.x) {
        float v = g_dinv[n] * g_acc[(size_t)n * HID + j] + bj;
        s += v;
        s2 += v * v;
    }
    atomicAdd(&g_sums[j], s);
    atomicAdd(&g_sumsq[j], s2);
}

// ---------------- K7: finalize BN affine -------------------------------------
__global__ void k_bnfin(const float* __restrict__ gamma, const float* __restrict__ beta) {
    int j = threadIdx.x;
    if (j >= HID) return;
    float inv_n = 1.0f / (float)N_NODES;
    float mu = g_sums[j] * inv_n;
    float var = g_sumsq[j] * inv_n - mu * mu;
    float inv = rsqrtf(var + BN_EPS);
    float sc = __ldg(gamma + j) * inv;
    g_scale[j] = sc;
    g_shift[j] = __ldg(beta + j) - mu * sc;
}

// ---------------- K8: BN + relu + 128->2 GEMV, pre-scaled by dinv[row] ------
__global__ __launch_bounds__(256) void k_node2(const float* __restrict__ b1,
                                               const float* __restrict__ W2) {
    int n = (blockIdx.x * blockDim.x + threadIdx.x) >> 5;
    int lane = threadIdx.x & 31;
    if (n >= N_NODES) return;
    float d = g_dinv[n];
    float4 v = *(const float4*)(g_acc + (size_t)n * HID + lane * 4);
    float vv[4] = {v.x, v.y, v.z, v.w};
    float o0 = 0.f, o1 = 0.f;
    #pragma unroll
    for (int q = 0; q < 4; ++q) {
        int j = lane * 4 + q;
        float h = fmaf(d * vv[q] + __ldg(b1 + j), g_scale[j], g_shift[j]);
        h = fmaxf(h, 0.f);
        o0 = fmaf(h, __ldg(W2 + j * 2 + 0), o0);
        o1 = fmaf(h, __ldg(W2 + j * 2 + 1), o1);
    }
    #pragma unroll
    for (int off = 16; off > 0; off >>= 1) {
        o0 += __shfl_xor_sync(0xffffffffu, o0, off);
        o1 += __shfl_xor_sync(0xffffffffu, o1, off);
    }
    if (lane == 0) {
        g_h2s[n * 2 + 0] = o0 * d;
        g_h2s[n * 2 + 1] = o1 * d;
    }
}

// ---------------- K9: layer-2 aggregation (gather) + bias -------------------
__global__ __launch_bounds__(256) void k_out(const float* __restrict__ b2,
                                             float* __restrict__ out) {
    int n = (blockIdx.x * blockDim.x + threadIdx.x) >> 5;
    int lane = threadIdx.x & 31;
    if (n >= N_NODES) return;
    int s = g_off[n], e = g_off[n + 1];
    float o0 = 0.f, o1 = 0.f;
    for (int i = s + lane; i < e; i += 32) {
        int r = g_csr_row[i];
        float2 v = *(const float2*)(g_h2s + (size_t)r * 2);
        o0 += v.x; o1 += v.y;
    }
    #pragma unroll
    for (int off = 16; off > 0; off >>= 1) {
        o0 += __shfl_xor_sync(0xffffffffu, o0, off);
        o1 += __shfl_xor_sync(0xffffffffu, o1, off);
    }
    if (lane == 0) {
        float d = g_dinv[n];
        float2 self = *(const float2*)(g_h2s + (size_t)n * 2);
        out[n * 2 + 0] = d * (o0 + self.x) + __ldg(b2 + 0);
        out[n * 2 + 1] = d * (o1 + self.y) + __ldg(b2 + 1);
    }
}

// ---------------- launch ----------------------------------------------------
extern "C" void kernel_launch(void* const* d_in, const int* in_sizes, int n_in,
                              void* d_out, int out_size) {
    const float* x  = (const float*)d_in[0];
    const int*   ei = (const int*)d_in[1];     // edge_index is int32
    const float* fi = (const float*)d_in[2];
    const float* W1 = (const float*)d_in[3];
    const float* b1 = (const float*)d_in[4];
    const float* W2 = (const float*)d_in[5];
    const float* b2 = (const float*)d_in[6];
    const float* gm = (const float*)d_in[7];
    const float* bt = (const float*)d_in[8];
    float* out = (float*)d_out;

    k_prep<<<(N_NODES + 255) / 256, 256>>>(W1, fi);
    k_deg<<<(N_EDGES / 4 + 255) / 256, 256>>>(ei);
    k_scan<<<1, 1024>>>();
    k_fill<<<(N_EDGES / 4 + 255) / 256, 256>>>(ei);
    k_gemm1<<<(N_NODES + GBM - 1) / GBM, 256>>>(x);
    {
        long long tot = (long long)N_NODES * 32;
        k_agg1<<<(unsigned)((tot + 255) / 256), 256>>>();
    }
    k_bnsum<<<1024, 128>>>(b1);
    k_bnfin<<<1, 128>>>(gm, bt);
    {
        long long tot = (long long)N_NODES * 32;
        k_node2<<<(unsigned)((tot + 255) / 256), 256>>>(b1, W2);
        k_out<<<(unsigned)((tot + 255) / 256), 256>>>(b2, out);
    }
}

// round 5
// speedup vs baseline: 1.9509x; 1.6728x over previous
#include <cuda_runtime.h>
#include <cuda_fp16.h>
#include <cstdint>
#include <cstddef>

#define N_NODES 100000
#define N_EDGES 3200000
#define IN_DIM  256
#define HID     128
#define OUT_DIM 2
#define BN_EPS  1e-5f

#define SC_BLOCKS 100
#define SC_THREADS 256
#define SC_PER 4   // 100*256*4 = 102400 >= N_NODES

// ---------------- scratch (static device globals; no runtime alloc) --------
__device__ __align__(16) float  g_dinv[N_NODES];
__device__ __align__(16) __half g_h1s[(size_t)N_NODES * HID];   // fp16 h1*dinv[row]
__device__ __align__(16) float  g_acc[(size_t)N_NODES * HID];   // fp32 aggregated
__device__ __align__(16) float  g_h2s[N_NODES * OUT_DIM];
__device__ __align__(16) float  g_W1s[IN_DIM * HID];
__device__ __align__(16) float  g_sums[HID];
__device__ __align__(16) float  g_sumsq[HID];
__device__ __align__(16) float  g_scale[HID];
__device__ __align__(16) float  g_shift[HID];
// CSR by destination
__device__ __align__(16) int    g_cnt[N_NODES];
__device__ __align__(16) int    g_off[N_NODES + 1];
__device__ __align__(16) int    g_cursor[N_NODES];
__device__ __align__(16) int    g_csr_row[N_EDGES];
// scan scratch
__device__ __align__(16) int    g_tpref[SC_BLOCKS * SC_THREADS];
__device__ __align__(16) int    g_bpart[SC_BLOCKS];

// ---------------- helpers ---------------------------------------------------
__device__ __forceinline__ float to_tf32(float x) {
    uint32_t u;
    asm("cvt.rna.tf32.f32 %0, %1;" : "=r"(u) : "f"(x));
    return __uint_as_float(u);
}

__device__ __forceinline__ void mma_tf32(float* c,
                                         uint32_t a0, uint32_t a1, uint32_t a2, uint32_t a3,
                                         uint32_t b0, uint32_t b1) {
    asm volatile(
        "mma.sync.aligned.m16n8k8.row.col.f32.tf32.tf32.f32 "
        "{%0,%1,%2,%3}, {%4,%5,%6,%7}, {%8,%9}, {%0,%1,%2,%3};"
        : "+f"(c[0]), "+f"(c[1]), "+f"(c[2]), "+f"(c[3])
        : "r"(a0), "r"(a1), "r"(a2), "r"(a3), "r"(b0), "r"(b1));
}

// ---------------- K0: prep + in-degree histogram (merged) -------------------
__global__ void k_prepdeg(const float* __restrict__ W1, const float* __restrict__ fi,
                          const int* __restrict__ ei) {
    int i = blockIdx.x * blockDim.x + threadIdx.x;
    if (i < IN_DIM * HID) {
        int k = i / HID;
        float s = 1.0f / (1.0f + __expf(-fi[k]));
        g_W1s[i] = W1[i] * s;
    }
    if (i < N_NODES) g_cnt[i] = 0;   // NOTE: histogram below must come after all zeroing
    if (i < HID) { g_sums[i] = 0.0f; g_sumsq[i] = 0.0f; }
    // grid-wide zeroing vs histogram race: zeroing and counting touch g_cnt.
    // Avoid the race by having this kernel ONLY zero + prep; histogram moved to k_deg.
    (void)ei;
}

__global__ void k_deg(const int* __restrict__ ei) {
    int t = blockIdx.x * blockDim.x + threadIdx.x;
    int e4 = t * 4;
    if (e4 >= N_EDGES) return;
    int4 c = *(const int4*)(ei + N_EDGES + e4);
    atomicAdd(&g_cnt[c.x], 1);
    atomicAdd(&g_cnt[c.y], 1);
    atomicAdd(&g_cnt[c.z], 1);
    atomicAdd(&g_cnt[c.w], 1);
}

// ---------------- K2a: per-thread chunk sums + block scan -------------------
__global__ __launch_bounds__(SC_THREADS) void k_scan1() {
    __shared__ int sm[SC_THREADS];
    int t = threadIdx.x, b = blockIdx.x;
    int base = (b * SC_THREADS + t) * SC_PER;
    int s = 0;
    #pragma unroll
    for (int q = 0; q < SC_PER; ++q) {
        int i = base + q;
        if (i < N_NODES) s += g_cnt[i];
    }
    sm[t] = s;
    __syncthreads();
    for (int off = 1; off < SC_THREADS; off <<= 1) {
        int v = (t >= off) ? sm[t - off] : 0;
        __syncthreads();
        sm[t] += v;
        __syncthreads();
    }
    g_tpref[b * SC_THREADS + t] = sm[t] - s;   // exclusive
    if (t == SC_THREADS - 1) g_bpart[b] = sm[t];
}

// ---------------- K2b: scan block partials (in smem) -------------------------
__global__ __launch_bounds__(128) void k_scan2() {
    __shared__ int sm[SC_BLOCKS];
    int t = threadIdx.x;
    if (t < SC_BLOCKS) sm[t] = g_bpart[t];
    __syncthreads();
    if (t == 0) {
        int run = 0;
        #pragma unroll 4
        for (int b = 0; b < SC_BLOCKS; ++b) { int c = sm[b]; sm[b] = run; run += c; }
    }
    __syncthreads();
    if (t < SC_BLOCKS) g_bpart[t] = sm[t];
}

// ---------------- K2c: finalize offsets, cursor, dinv ------------------------
__global__ __launch_bounds__(SC_THREADS) void k_scan3() {
    int t = threadIdx.x, b = blockIdx.x;
    int tid_g = b * SC_THREADS + t;
    int base = tid_g * SC_PER;
    int run = g_bpart[b] + g_tpref[tid_g];
    #pragma unroll
    for (int q = 0; q < SC_PER; ++q) {
        int i = base + q;
        if (i < N_NODES) {
            int c = g_cnt[i];
            g_off[i] = run;
            g_cursor[i] = run;
            g_dinv[i] = rsqrtf((float)(c + 1));
            run += c;
            if (i == N_NODES - 1) g_off[N_NODES] = run;
        }
    }
}

// ---------------- K3: fill CSR source indices (4 edges per thread) ----------
__global__ void k_fill(const int* __restrict__ ei) {
    int t = blockIdx.x * blockDim.x + threadIdx.x;
    int e4 = t * 4;
    if (e4 >= N_EDGES) return;
    int4 r = *(const int4*)(ei + e4);
    int4 c = *(const int4*)(ei + N_EDGES + e4);
    int p0 = atomicAdd(&g_cursor[c.x], 1);
    int p1 = atomicAdd(&g_cursor[c.y], 1);
    int p2 = atomicAdd(&g_cursor[c.z], 1);
    int p3 = atomicAdd(&g_cursor[c.w], 1);
    g_csr_row[p0] = r.x;
    g_csr_row[p1] = r.y;
    g_csr_row[p2] = r.z;
    g_csr_row[p3] = r.w;
}

// ---------------- K4: GEMM1 (tf32): h1s(fp16) = (x @ W1s)*dinv[row] ---------
#define GBM 128
#define GBK 32
#define A_S 36
#define B_S 132
__global__ __launch_bounds__(256) void k_gemm1(const float* __restrict__ x) {
    __shared__ float As[GBM * A_S];
    __shared__ float Bs[GBK * B_S];
    const int m0   = blockIdx.x * GBM;
    const int tid  = threadIdx.x;
    const int lane = tid & 31;
    const int wid  = tid >> 5;
    const int wm   = wid >> 2;
    const int wn   = wid & 3;
    const int grp  = lane >> 2;
    const int tg   = lane & 3;

    float acc[4][4][4];
    #pragma unroll
    for (int im = 0; im < 4; ++im)
        #pragma unroll
        for (int in = 0; in < 4; ++in)
            #pragma unroll
            for (int q = 0; q < 4; ++q) acc[im][in][q] = 0.f;

    for (int k0 = 0; k0 < IN_DIM; k0 += GBK) {
        #pragma unroll
        for (int p = 0; p < 4; ++p) {
            int slot = tid + p * 256;
            int r = slot >> 3;
            int q = slot & 7;
            int gm = m0 + r;
            float4 v = make_float4(0.f, 0.f, 0.f, 0.f);
            if (gm < N_NODES)
                v = *(const float4*)(x + (size_t)gm * IN_DIM + k0 + q * 4);
            float* dst = As + r * A_S + q * 4;
            dst[0] = to_tf32(v.x);
            dst[1] = to_tf32(v.y);
            dst[2] = to_tf32(v.z);
            dst[3] = to_tf32(v.w);
        }
        #pragma unroll
        for (int p = 0; p < 4; ++p) {
            int slot = tid + p * 256;
            int r = slot >> 5;
            int c = slot & 31;
            float4 v = *(const float4*)(g_W1s + (size_t)(k0 + r) * HID + c * 4);
            float* dst = Bs + r * B_S + c * 4;
            dst[0] = to_tf32(v.x);
            dst[1] = to_tf32(v.y);
            dst[2] = to_tf32(v.z);
            dst[3] = to_tf32(v.w);
        }
        __syncthreads();

        #pragma unroll
        for (int ks = 0; ks < GBK; ks += 8) {
            uint32_t a[4][4], b[4][2];
            #pragma unroll
            for (int im = 0; im < 4; ++im) {
                int mb = wm * 64 + im * 16;
                const float* pa = As + (mb + grp) * A_S + ks + tg;
                a[im][0] = __float_as_uint(pa[0]);
                a[im][1] = __float_as_uint(pa[8 * A_S]);
                a[im][2] = __float_as_uint(pa[4]);
                a[im][3] = __float_as_uint(pa[8 * A_S + 4]);
            }
            #pragma unroll
            for (int in = 0; in < 4; ++in) {
                int nb = wn * 32 + in * 8 + grp;
                const float* pb = Bs + (ks + tg) * B_S + nb;
                b[in][0] = __float_as_uint(pb[0]);
                b[in][1] = __float_as_uint(pb[4 * B_S]);
            }
            #pragma unroll
            for (int im = 0; im < 4; ++im)
                #pragma unroll
                for (int in = 0; in < 4; ++in)
                    mma_tf32(acc[im][in], a[im][0], a[im][1], a[im][2], a[im][3],
                             b[in][0], b[in][1]);
        }
        __syncthreads();
    }

    // epilogue: scale by dinv[row], write fp16 h1s
    #pragma unroll
    for (int im = 0; im < 4; ++im) {
        int r0 = m0 + wm * 64 + im * 16 + grp;
        int r1 = r0 + 8;
        float d0 = (r0 < N_NODES) ? g_dinv[r0] : 0.f;
        float d1 = (r1 < N_NODES) ? g_dinv[r1] : 0.f;
        #pragma unroll
        for (int in = 0; in < 4; ++in) {
            int col = wn * 32 + in * 8 + tg * 2;
            if (r0 < N_NODES) {
                __half2 h = __floats2half2_rn(acc[im][in][0] * d0, acc[im][in][1] * d0);
                *(__half2*)(g_h1s + (size_t)r0 * HID + col) = h;
            }
            if (r1 < N_NODES) {
                __half2 h = __floats2half2_rn(acc[im][in][2] * d1, acc[im][in][3] * d1);
                *(__half2*)(g_h1s + (size_t)r1 * HID + col) = h;
            }
        }
    }
}

// ---------------- K5: layer-1 aggregation (fp16 gather) + fused BN stats ----
__global__ __launch_bounds__(256) void k_agg1(const float* __restrict__ b1) {
    __shared__ float s_sum[HID];
    __shared__ float s_sq[HID];
    const int tid  = threadIdx.x;
    const int lane = tid & 31;
    const int warp = tid >> 5;
    if (tid < HID) { s_sum[tid] = 0.f; s_sq[tid] = 0.f; }
    __syncthreads();

    int n = blockIdx.x * 8 + warp;
    if (n < N_NODES) {
        int s = g_off[n], e = g_off[n + 1];
        float4 v0, v1 = make_float4(0.f, 0.f, 0.f, 0.f);
        {   // self-loop seed
            uint2 u = ((const uint2*)(g_h1s + (size_t)n * HID))[lane];
            float2 fa = __half22float2(*(__half2*)&u.x);
            float2 fb = __half22float2(*(__half2*)&u.y);
            v0 = make_float4(fa.x, fa.y, fb.x, fb.y);
        }
        int i = s;
        for (; i + 2 <= e; i += 2) {
            int r0 = g_csr_row[i];
            int r1 = g_csr_row[i + 1];
            uint2 u0 = ((const uint2*)(g_h1s + (size_t)r0 * HID))[lane];
            uint2 u1 = ((const uint2*)(g_h1s + (size_t)r1 * HID))[lane];
            float2 a0 = __half22float2(*(__half2*)&u0.x);
            float2 b0 = __half22float2(*(__half2*)&u0.y);
            float2 a1 = __half22float2(*(__half2*)&u1.x);
            float2 b1f = __half22float2(*(__half2*)&u1.y);
            v0.x += a0.x; v0.y += a0.y; v0.z += b0.x; v0.w += b0.y;
            v1.x += a1.x; v1.y += a1.y; v1.z += b1f.x; v1.w += b1f.y;
        }
        if (i < e) {
            int r0 = g_csr_row[i];
            uint2 u0 = ((const uint2*)(g_h1s + (size_t)r0 * HID))[lane];
            float2 a0 = __half22float2(*(__half2*)&u0.x);
            float2 b0 = __half22float2(*(__half2*)&u0.y);
            v0.x += a0.x; v0.y += a0.y; v0.z += b0.x; v0.w += b0.y;
        }
        v0.x += v1.x; v0.y += v1.y; v0.z += v1.z; v0.w += v1.w;
        *(float4*)(g_acc + (size_t)n * HID + lane * 4) = v0;

        // fused BN statistics: h = dinv[n]*acc + b1[j]
        float d = g_dinv[n];
        float vv[4] = {v0.x, v0.y, v0.z, v0.w};
        #pragma unroll
        for (int q = 0; q < 4; ++q) {
            int j = lane * 4 + q;
            float h = fmaf(d, vv[q], __ldg(b1 + j));
            atomicAdd(&s_sum[j], h);
            atomicAdd(&s_sq[j], h * h);
        }
    }
    __syncthreads();
    if (tid < HID) {
        atomicAdd(&g_sums[tid], s_sum[tid]);
        atomicAdd(&g_sumsq[tid], s_sq[tid]);
    }
}

// ---------------- K7: finalize BN affine -------------------------------------
__global__ void k_bnfin(const float* __restrict__ gamma, const float* __restrict__ beta) {
    int j = threadIdx.x;
    if (j >= HID) return;
    float inv_n = 1.0f / (float)N_NODES;
    float mu = g_sums[j] * inv_n;
    float var = g_sumsq[j] * inv_n - mu * mu;
    float inv = rsqrtf(var + BN_EPS);
    float sc = __ldg(gamma + j) * inv;
    g_scale[j] = sc;
    g_shift[j] = __ldg(beta + j) - mu * sc;
}

// ---------------- K8: BN + relu + 128->2 GEMV, pre-scaled by dinv[row] ------
__global__ __launch_bounds__(256) void k_node2(const float* __restrict__ b1,
                                               const float* __restrict__ W2) {
    int n = (blockIdx.x * blockDim.x + threadIdx.x) >> 5;
    int lane = threadIdx.x & 31;
    if (n >= N_NODES) return;
    float d = g_dinv[n];
    float4 v = *(const float4*)(g_acc + (size_t)n * HID + lane * 4);
    float vv[4] = {v.x, v.y, v.z, v.w};
    float o0 = 0.f, o1 = 0.f;
    #pragma unroll
    for (int q = 0; q < 4; ++q) {
        int j = lane * 4 + q;
        float h = fmaf(d * vv[q] + __ldg(b1 + j), g_scale[j], g_shift[j]);
        h = fmaxf(h, 0.f);
        o0 = fmaf(h, __ldg(W2 + j * 2 + 0), o0);
        o1 = fmaf(h, __ldg(W2 + j * 2 + 1), o1);
    }
    #pragma unroll
    for (int off = 16; off > 0; off >>= 1) {
        o0 += __shfl_xor_sync(0xffffffffu, o0, off);
        o1 += __shfl_xor_sync(0xffffffffu, o1, off);
    }
    if (lane == 0) {
        g_h2s[n * 2 + 0] = o0 * d;
        g_h2s[n * 2 + 1] = o1 * d;
    }
}

// ---------------- K9: layer-2 aggregation (gather) + bias -------------------
__global__ __launch_bounds__(256) void k_out(const float* __restrict__ b2,
                                             float* __restrict__ out) {
    int n = (blockIdx.x * blockDim.x + threadIdx.x) >> 5;
    int lane = threadIdx.x & 31;
    if (n >= N_NODES) return;
    int s = g_off[n], e = g_off[n + 1];
    float o0 = 0.f, o1 = 0.f;
    for (int i = s + lane; i < e; i += 32) {
        int r = g_csr_row[i];
        float2 v = *(const float2*)(g_h2s + (size_t)r * 2);
        o0 += v.x; o1 += v.y;
    }
    #pragma unroll
    for (int off = 16; off > 0; off >>= 1) {
        o0 += __shfl_xor_sync(0xffffffffu, o0, off);
        o1 += __shfl_xor_sync(0xffffffffu, o1, off);
    }
    if (lane == 0) {
        float d = g_dinv[n];
        float2 self = *(const float2*)(g_h2s + (size_t)n * 2);
        out[n * 2 + 0] = d * (o0 + self.x) + __ldg(b2 + 0);
        out[n * 2 + 1] = d * (o1 + self.y) + __ldg(b2 + 1);
    }
}

// ---------------- launch ----------------------------------------------------
extern "C" void kernel_launch(void* const* d_in, const int* in_sizes, int n_in,
                              void* d_out, int out_size) {
    const float* x  = (const float*)d_in[0];
    const int*   ei = (const int*)d_in[1];
    const float* fi = (const float*)d_in[2];
    const float* W1 = (const float*)d_in[3];
    const float* b1 = (const float*)d_in[4];
    const float* W2 = (const float*)d_in[5];
    const float* b2 = (const float*)d_in[6];
    const float* gm = (const float*)d_in[7];
    const float* bt = (const float*)d_in[8];
    float* out = (float*)d_out;

    k_prepdeg<<<(N_NODES + 255) / 256, 256>>>(W1, fi, ei);
    k_deg<<<(N_EDGES / 4 + 255) / 256, 256>>>(ei);
    k_scan1<<<SC_BLOCKS, SC_THREADS>>>();
    k_scan2<<<1, 128>>>();
    k_scan3<<<SC_BLOCKS, SC_THREADS>>>();
    k_fill<<<(N_EDGES / 4 + 255) / 256, 256>>>(ei);
    k_gemm1<<<(N_NODES + GBM - 1) / GBM, 256>>>(x);
    k_agg1<<<(N_NODES + 7) / 8, 256>>>(b1);
    k_bnfin<<<1, 128>>>(gm, bt);
    {
        long long tot = (long long)N_NODES * 32;
        k_node2<<<(unsigned)((tot + 255) / 256), 256>>>(b1, W2);
        k_out<<<(unsigned)((tot + 255) / 256), 256>>>(b2, out);
    }
}

// round 6
// speedup vs baseline: 1.9726x; 1.0111x over previous
#include <cuda_runtime.h>
#include <cuda_fp16.h>
#include <cstdint>
#include <cstddef>

#define N_NODES 100000
#define N_EDGES 3200000
#define IN_DIM  256
#define HID     128
#define OUT_DIM 2
#define BN_EPS  1e-5f

#define SC_BLOCKS 100
#define SC_THREADS 256
#define SC_PER 4   // 100*256*4 = 102400 >= N_NODES

// ---------------- scratch (static device globals; no runtime alloc) --------
__device__ __align__(16) float  g_dinv[N_NODES];
__device__ __align__(16) __half g_h1s[(size_t)N_NODES * HID];   // fp16 h1*dinv[row]
__device__ __align__(16) __half g_hpre[(size_t)N_NODES * HID];  // fp16 pre-BN h
__device__ __align__(16) float  g_h2s[N_NODES * OUT_DIM];
__device__ __align__(16) float  g_W1s[IN_DIM * HID];
__device__ __align__(16) float  g_sums[HID];
__device__ __align__(16) float  g_sumsq[HID];
__device__ __align__(16) float  g_scale[HID];
__device__ __align__(16) float  g_shift[HID];
// CSR by destination
__device__ __align__(16) int    g_cnt[N_NODES];
__device__ __align__(16) int    g_off[N_NODES + 1];
__device__ __align__(16) int    g_cursor[N_NODES];
__device__ __align__(16) int    g_csr_row[N_EDGES];
// scan scratch
__device__ __align__(16) int    g_tpref[SC_BLOCKS * SC_THREADS];
__device__ __align__(16) int    g_bpart[SC_BLOCKS];

// ---------------- helpers ---------------------------------------------------
__device__ __forceinline__ float to_tf32(float x) {
    uint32_t u;
    asm("cvt.rna.tf32.f32 %0, %1;" : "=r"(u) : "f"(x));
    return __uint_as_float(u);
}

__device__ __forceinline__ void mma_tf32(float* c,
                                         uint32_t a0, uint32_t a1, uint32_t a2, uint32_t a3,
                                         uint32_t b0, uint32_t b1) {
    asm volatile(
        "mma.sync.aligned.m16n8k8.row.col.f32.tf32.tf32.f32 "
        "{%0,%1,%2,%3}, {%4,%5,%6,%7}, {%8,%9}, {%0,%1,%2,%3};"
        : "+f"(c[0]), "+f"(c[1]), "+f"(c[2]), "+f"(c[3])
        : "r"(a0), "r"(a1), "r"(a2), "r"(a3), "r"(b0), "r"(b1));
}

// ---------------- K0: prep (fold sigmoid into W1, zero counters) ------------
__global__ void k_prep(const float* __restrict__ W1, const float* __restrict__ fi) {
    int i = blockIdx.x * blockDim.x + threadIdx.x;
    if (i < IN_DIM * HID) {
        int k = i / HID;
        float s = 1.0f / (1.0f + __expf(-fi[k]));
        g_W1s[i] = W1[i] * s;
    }
    if (i < N_NODES) g_cnt[i] = 0;
    if (i < HID) { g_sums[i] = 0.0f; g_sumsq[i] = 0.0f; }
}

// ---------------- K1: in-degree histogram (8 edges per thread) --------------
__global__ void k_deg(const int* __restrict__ ei) {
    int t = blockIdx.x * blockDim.x + threadIdx.x;
    int e8 = t * 8;
    if (e8 >= N_EDGES) return;
    int4 c0 = *(const int4*)(ei + N_EDGES + e8);
    int4 c1 = *(const int4*)(ei + N_EDGES + e8 + 4);
    atomicAdd(&g_cnt[c0.x], 1);
    atomicAdd(&g_cnt[c0.y], 1);
    atomicAdd(&g_cnt[c0.z], 1);
    atomicAdd(&g_cnt[c0.w], 1);
    atomicAdd(&g_cnt[c1.x], 1);
    atomicAdd(&g_cnt[c1.y], 1);
    atomicAdd(&g_cnt[c1.z], 1);
    atomicAdd(&g_cnt[c1.w], 1);
}

// ---------------- K2a: per-thread chunk sums + block scan -------------------
__global__ __launch_bounds__(SC_THREADS) void k_scan1() {
    __shared__ int sm[SC_THREADS];
    int t = threadIdx.x, b = blockIdx.x;
    int base = (b * SC_THREADS + t) * SC_PER;
    int s = 0;
    #pragma unroll
    for (int q = 0; q < SC_PER; ++q) {
        int i = base + q;
        if (i < N_NODES) s += g_cnt[i];
    }
    sm[t] = s;
    __syncthreads();
    for (int off = 1; off < SC_THREADS; off <<= 1) {
        int v = (t >= off) ? sm[t - off] : 0;
        __syncthreads();
        sm[t] += v;
        __syncthreads();
    }
    g_tpref[b * SC_THREADS + t] = sm[t] - s;   // exclusive
    if (t == SC_THREADS - 1) g_bpart[b] = sm[t];
}

// ---------------- K2b: scan block partials (parallel) ------------------------
__global__ __launch_bounds__(128) void k_scan2() {
    __shared__ int sm[128];
    int t = threadIdx.x;
    int v = (t < SC_BLOCKS) ? g_bpart[t] : 0;
    sm[t] = v;
    __syncthreads();
    for (int off = 1; off < 128; off <<= 1) {
        int u = (t >= off) ? sm[t - off] : 0;
        __syncthreads();
        sm[t] += u;
        __syncthreads();
    }
    if (t < SC_BLOCKS) g_bpart[t] = sm[t] - v;   // exclusive
}

// ---------------- K2c: finalize offsets, cursor, dinv ------------------------
__global__ __launch_bounds__(SC_THREADS) void k_scan3() {
    int t = threadIdx.x, b = blockIdx.x;
    int tid_g = b * SC_THREADS + t;
    int base = tid_g * SC_PER;
    int run = g_bpart[b] + g_tpref[tid_g];
    #pragma unroll
    for (int q = 0; q < SC_PER; ++q) {
        int i = base + q;
        if (i < N_NODES) {
            int c = g_cnt[i];
            g_off[i] = run;
            g_cursor[i] = run;
            g_dinv[i] = rsqrtf((float)(c + 1));
            run += c;
            if (i == N_NODES - 1) g_off[N_NODES] = run;
        }
    }
}

// ---------------- K3: fill CSR source indices (8 edges per thread) ----------
__global__ void k_fill(const int* __restrict__ ei) {
    int t = blockIdx.x * blockDim.x + threadIdx.x;
    int e8 = t * 8;
    if (e8 >= N_EDGES) return;
    int4 r0 = *(const int4*)(ei + e8);
    int4 r1 = *(const int4*)(ei + e8 + 4);
    int4 c0 = *(const int4*)(ei + N_EDGES + e8);
    int4 c1 = *(const int4*)(ei + N_EDGES + e8 + 4);
    int p0 = atomicAdd(&g_cursor[c0.x], 1);
    int p1 = atomicAdd(&g_cursor[c0.y], 1);
    int p2 = atomicAdd(&g_cursor[c0.z], 1);
    int p3 = atomicAdd(&g_cursor[c0.w], 1);
    int p4 = atomicAdd(&g_cursor[c1.x], 1);
    int p5 = atomicAdd(&g_cursor[c1.y], 1);
    int p6 = atomicAdd(&g_cursor[c1.z], 1);
    int p7 = atomicAdd(&g_cursor[c1.w], 1);
    g_csr_row[p0] = r0.x;
    g_csr_row[p1] = r0.y;
    g_csr_row[p2] = r0.z;
    g_csr_row[p3] = r0.w;
    g_csr_row[p4] = r1.x;
    g_csr_row[p5] = r1.y;
    g_csr_row[p6] = r1.z;
    g_csr_row[p7] = r1.w;
}

// ---------------- K4: GEMM1 (tf32, A prefetch): h1s(fp16) = (x@W1s)*dinv ----
#define GBM 128
#define GBK 32
#define A_S 36
#define B_S 132
__global__ __launch_bounds__(256, 2) void k_gemm1(const float* __restrict__ x) {
    __shared__ float As[GBM * A_S];
    __shared__ float Bs[GBK * B_S];
    const int m0   = blockIdx.x * GBM;
    const int tid  = threadIdx.x;
    const int lane = tid & 31;
    const int wid  = tid >> 5;
    const int wm   = wid >> 2;
    const int wn   = wid & 3;
    const int grp  = lane >> 2;
    const int tg   = lane & 3;

    float acc[4][4][4];
    #pragma unroll
    for (int im = 0; im < 4; ++im)
        #pragma unroll
        for (int in = 0; in < 4; ++in)
            #pragma unroll
            for (int q = 0; q < 4; ++q) acc[im][in][q] = 0.f;

    // A staging registers (4 float4 per thread)
    float4 ra[4];
    const int a_r = tid >> 3;          // base row slot helper (slot = tid + p*256)
    (void)a_r;

    auto loadA = [&](int k0) {
        #pragma unroll
        for (int p = 0; p < 4; ++p) {
            int slot = tid + p * 256;
            int r = slot >> 3;
            int q = slot & 7;
            int gm = m0 + r;
            ra[p] = make_float4(0.f, 0.f, 0.f, 0.f);
            if (gm < N_NODES)
                ra[p] = *(const float4*)(x + (size_t)gm * IN_DIM + k0 + q * 4);
        }
    };
    auto storeA = [&]() {
        #pragma unroll
        for (int p = 0; p < 4; ++p) {
            int slot = tid + p * 256;
            int r = slot >> 3;
            int q = slot & 7;
            float* dst = As + r * A_S + q * 4;
            dst[0] = to_tf32(ra[p].x);
            dst[1] = to_tf32(ra[p].y);
            dst[2] = to_tf32(ra[p].z);
            dst[3] = to_tf32(ra[p].w);
        }
    };
    auto loadstoreB = [&](int k0) {
        #pragma unroll
        for (int p = 0; p < 4; ++p) {
            int slot = tid + p * 256;
            int r = slot >> 5;
            int c = slot & 31;
            float4 v = *(const float4*)(g_W1s + (size_t)(k0 + r) * HID + c * 4);
            float* dst = Bs + r * B_S + c * 4;
            dst[0] = to_tf32(v.x);
            dst[1] = to_tf32(v.y);
            dst[2] = to_tf32(v.z);
            dst[3] = to_tf32(v.w);
        }
    };

    const int NT = IN_DIM / GBK;   // 8
    loadA(0);
    for (int t = 0; t < NT; ++t) {
        storeA();
        loadstoreB(t * GBK);
        __syncthreads();
        if (t + 1 < NT) loadA((t + 1) * GBK);   // prefetch next A while computing

        #pragma unroll
        for (int ks = 0; ks < GBK; ks += 8) {
            uint32_t a[4][4], b[4][2];
            #pragma unroll
            for (int im = 0; im < 4; ++im) {
                int mb = wm * 64 + im * 16;
                const float* pa = As + (mb + grp) * A_S + ks + tg;
                a[im][0] = __float_as_uint(pa[0]);
                a[im][1] = __float_as_uint(pa[8 * A_S]);
                a[im][2] = __float_as_uint(pa[4]);
                a[im][3] = __float_as_uint(pa[8 * A_S + 4]);
            }
            #pragma unroll
            for (int in = 0; in < 4; ++in) {
                int nb = wn * 32 + in * 8 + grp;
                const float* pb = Bs + (ks + tg) * B_S + nb;
                b[in][0] = __float_as_uint(pb[0]);
                b[in][1] = __float_as_uint(pb[4 * B_S]);
            }
            #pragma unroll
            for (int im = 0; im < 4; ++im)
                #pragma unroll
                for (int in = 0; in < 4; ++in)
                    mma_tf32(acc[im][in], a[im][0], a[im][1], a[im][2], a[im][3],
                             b[in][0], b[in][1]);
        }
        __syncthreads();
    }

    // epilogue: scale by dinv[row], write fp16 h1s
    #pragma unroll
    for (int im = 0; im < 4; ++im) {
        int r0 = m0 + wm * 64 + im * 16 + grp;
        int r1 = r0 + 8;
        float d0 = (r0 < N_NODES) ? g_dinv[r0] : 0.f;
        float d1 = (r1 < N_NODES) ? g_dinv[r1] : 0.f;
        #pragma unroll
        for (int in = 0; in < 4; ++in) {
            int col = wn * 32 + in * 8 + tg * 2;
            if (r0 < N_NODES) {
                __half2 h = __floats2half2_rn(acc[im][in][0] * d0, acc[im][in][1] * d0);
                *(__half2*)(g_h1s + (size_t)r0 * HID + col) = h;
            }
            if (r1 < N_NODES) {
                __half2 h = __floats2half2_rn(acc[im][in][2] * d1, acc[im][in][3] * d1);
                *(__half2*)(g_h1s + (size_t)r1 * HID + col) = h;
            }
        }
    }
}

// ---------------- K5: layer-1 aggregation + fused BN stats, fp16 h out ------
__global__ __launch_bounds__(256) void k_agg1(const float* __restrict__ b1) {
    __shared__ float s_sum[HID];
    __shared__ float s_sq[HID];
    const int tid  = threadIdx.x;
    const int lane = tid & 31;
    const int warp = tid >> 5;
    if (tid < HID) { s_sum[tid] = 0.f; s_sq[tid] = 0.f; }
    __syncthreads();

    int n = blockIdx.x * 8 + warp;
    if (n < N_NODES) {
        int s = g_off[n], e = g_off[n + 1];
        float4 v0, v1 = make_float4(0.f, 0.f, 0.f, 0.f);
        {
            uint2 u = ((const uint2*)(g_h1s + (size_t)n * HID))[lane];
            float2 fa = __half22float2(*(__half2*)&u.x);
            float2 fb = __half22float2(*(__half2*)&u.y);
            v0 = make_float4(fa.x, fa.y, fb.x, fb.y);
        }
        int i = s;
        for (; i + 2 <= e; i += 2) {
            int r0 = g_csr_row[i];
            int r1 = g_csr_row[i + 1];
            uint2 u0 = ((const uint2*)(g_h1s + (size_t)r0 * HID))[lane];
            uint2 u1 = ((const uint2*)(g_h1s + (size_t)r1 * HID))[lane];
            float2 a0 = __half22float2(*(__half2*)&u0.x);
            float2 b0 = __half22float2(*(__half2*)&u0.y);
            float2 a1 = __half22float2(*(__half2*)&u1.x);
            float2 b1f = __half22float2(*(__half2*)&u1.y);
            v0.x += a0.x; v0.y += a0.y; v0.z += b0.x; v0.w += b0.y;
            v1.x += a1.x; v1.y += a1.y; v1.z += b1f.x; v1.w += b1f.y;
        }
        if (i < e) {
            int r0 = g_csr_row[i];
            uint2 u0 = ((const uint2*)(g_h1s + (size_t)r0 * HID))[lane];
            float2 a0 = __half22float2(*(__half2*)&u0.x);
            float2 b0 = __half22float2(*(__half2*)&u0.y);
            v0.x += a0.x; v0.y += a0.y; v0.z += b0.x; v0.w += b0.y;
        }
        v0.x += v1.x; v0.y += v1.y; v0.z += v1.z; v0.w += v1.w;

        // h = dinv[n]*agg + b1[j]  (pre-BN activation), store fp16 + stats
        float d = g_dinv[n];
        float vv[4] = {v0.x, v0.y, v0.z, v0.w};
        float hh[4];
        #pragma unroll
        for (int q = 0; q < 4; ++q) {
            int j = lane * 4 + q;
            hh[q] = fmaf(d, vv[q], __ldg(b1 + j));
            atomicAdd(&s_sum[j], hh[q]);
            atomicAdd(&s_sq[j], hh[q] * hh[q]);
        }
        uint2 o;
        *(__half2*)&o.x = __floats2half2_rn(hh[0], hh[1]);
        *(__half2*)&o.y = __floats2half2_rn(hh[2], hh[3]);
        ((uint2*)(g_hpre + (size_t)n * HID))[lane] = o;
    }
    __syncthreads();
    if (tid < HID) {
        atomicAdd(&g_sums[tid], s_sum[tid]);
        atomicAdd(&g_sumsq[tid], s_sq[tid]);
    }
}

// ---------------- K7: finalize BN affine -------------------------------------
__global__ void k_bnfin(const float* __restrict__ gamma, const float* __restrict__ beta) {
    int j = threadIdx.x;
    if (j >= HID) return;
    float inv_n = 1.0f / (float)N_NODES;
    float mu = g_sums[j] * inv_n;
    float var = g_sumsq[j] * inv_n - mu * mu;
    float inv = rsqrtf(var + BN_EPS);
    float sc = __ldg(gamma + j) * inv;
    g_scale[j] = sc;
    g_shift[j] = __ldg(beta + j) - mu * sc;
}

// ---------------- K8: BN affine + relu + 128->2 GEMV ------------------------
__global__ __launch_bounds__(256) void k_node2(const float* __restrict__ W2) {
    int n = (blockIdx.x * blockDim.x + threadIdx.x) >> 5;
    int lane = threadIdx.x & 31;
    if (n >= N_NODES) return;
    uint2 u = ((const uint2*)(g_hpre + (size_t)n * HID))[lane];
    float2 fa = __half22float2(*(__half2*)&u.x);
    float2 fb = __half22float2(*(__half2*)&u.y);
    float vv[4] = {fa.x, fa.y, fb.x, fb.y};
    float o0 = 0.f, o1 = 0.f;
    #pragma unroll
    for (int q = 0; q < 4; ++q) {
        int j = lane * 4 + q;
        float h = fmaf(vv[q], g_scale[j], g_shift[j]);
        h = fmaxf(h, 0.f);
        o0 = fmaf(h, __ldg(W2 + j * 2 + 0), o0);
        o1 = fmaf(h, __ldg(W2 + j * 2 + 1), o1);
    }
    #pragma unroll
    for (int off = 16; off > 0; off >>= 1) {
        o0 += __shfl_xor_sync(0xffffffffu, o0, off);
        o1 += __shfl_xor_sync(0xffffffffu, o1, off);
    }
    if (lane == 0) {
        float d = g_dinv[n];
        g_h2s[n * 2 + 0] = o0 * d;
        g_h2s[n * 2 + 1] = o1 * d;
    }
}

// ---------------- K9: layer-2 aggregation (gather) + bias -------------------
__global__ __launch_bounds__(256) void k_out(const float* __restrict__ b2,
                                             float* __restrict__ out) {
    int n = (blockIdx.x * blockDim.x + threadIdx.x) >> 5;
    int lane = threadIdx.x & 31;
    if (n >= N_NODES) return;
    int s = g_off[n], e = g_off[n + 1];
    float o0 = 0.f, o1 = 0.f;
    for (int i = s + lane; i < e; i += 32) {
        int r = g_csr_row[i];
        float2 v = *(const float2*)(g_h2s + (size_t)r * 2);
        o0 += v.x; o1 += v.y;
    }
    #pragma unroll
    for (int off = 16; off > 0; off >>= 1) {
        o0 += __shfl_xor_sync(0xffffffffu, o0, off);
        o1 += __shfl_xor_sync(0xffffffffu, o1, off);
    }
    if (lane == 0) {
        float d = g_dinv[n];
        float2 self = *(const float2*)(g_h2s + (size_t)n * 2);
        out[n * 2 + 0] = d * (o0 + self.x) + __ldg(b2 + 0);
        out[n * 2 + 1] = d * (o1 + self.y) + __ldg(b2 + 1);
    }
}

// ---------------- launch ----------------------------------------------------
extern "C" void kernel_launch(void* const* d_in, const int* in_sizes, int n_in,
                              void* d_out, int out_size) {
    const float* x  = (const float*)d_in[0];
    const int*   ei = (const int*)d_in[1];
    const float* fi = (const float*)d_in[2];
    const float* W1 = (const float*)d_in[3];
    const float* b1 = (const float*)d_in[4];
    const float* W2 = (const float*)d_in[5];
    const float* b2 = (const float*)d_in[6];
    const float* gm = (const float*)d_in[7];
    const float* bt = (const float*)d_in[8];
    float* out = (float*)d_out;

    k_prep<<<(N_NODES + 255) / 256, 256>>>(W1, fi);
    k_deg<<<(N_EDGES / 8 + 255) / 256, 256>>>(ei);
    k_scan1<<<SC_BLOCKS, SC_THREADS>>>();
    k_scan2<<<1, 128>>>();
    k_scan3<<<SC_BLOCKS, SC_THREADS>>>();
    k_fill<<<(N_EDGES / 8 + 255) / 256, 256>>>(ei);
    k_gemm1<<<(N_NODES + GBM - 1) / GBM, 256>>>(x);
    k_agg1<<<(N_NODES + 7) / 8, 256>>>(b1);
    k_bnfin<<<1, 128>>>(gm, bt);
    {
        long long tot = (long long)N_NODES * 32;
        k_node2<<<(unsigned)((tot + 255) / 256), 256>>>(W2);
        k_out<<<(unsigned)((tot + 255) / 256), 256>>>(b2, out);
    }
}